// round 9
// baseline (speedup 1.0000x reference)
#include <cuda_runtime.h>
#include <cuda_bf16.h>
#include <cuda_fp16.h>
#include <cstdint>
#include <math.h>

#define N_NODES 50000
#define N_EDGES 800000
#define IN_CH 128
#define OUT_CH 32
#define HEADS 4
#define N_TYPES 4
#define N_CONF 5
#define D_OUT 128                 /* HEADS*OUT_CH */
#define SEG (N_TYPES * N_NODES)   /* 200000 (dst,type) segments */
#define SCAN_BLOCKS ((SEG + 1023) / 1024)   /* 196 */
#define SROW 20                   /* floats per (t,n) score row */

/* ------------------------- device scratch (static, no allocation) ---------- */
__device__ float g_xt[(size_t)N_TYPES * N_NODES * D_OUT];          /* 102.4 MB */
__device__ __half g_xt_h[(size_t)N_TYPES * N_NODES * D_OUT];       /* 51.2 MB */
__device__ float g_si[(size_t)N_TYPES * N_NODES * SROW];           /* 16 MB */
__device__ float g_sj[(size_t)N_TYPES * N_NODES * SROW];           /* 16 MB */
__device__ int   g_cnt[SEG];
__device__ int   g_offs[SEG + 1];
__device__ int   g_cursor[SEG];
__device__ int   g_rec[N_EDGES];                                   /* 3.2 MB, src|t<<16 */
__device__ int   g_bsum[SCAN_BLOCKS];
__device__ __nv_bfloat16 g_wh[(size_t)N_TYPES * D_OUT * IN_CH];    /* [t][o][k] */
__device__ __nv_bfloat16 g_wl[(size_t)N_TYPES * D_OUT * IN_CH];

__device__ __forceinline__ uint32_t smem_u32(const void* p) {
    uint32_t a;
    asm("{ .reg .u64 t; cvta.to.shared.u64 t, %1; cvt.u32.u64 %0, t; }"
        : "=r"(a) : "l"(p));
    return a;
}
__device__ __forceinline__ float sel4(const float* a, int t) {
    return t == 0 ? a[0] : t == 1 ? a[1] : t == 2 ? a[2] : a[3];
}

/* ============================================================================
 * K0: split + transpose W: [t][k][o] fp32 -> [t][o][k] bf16 hi/lo
 * ==========================================================================*/
__global__ __launch_bounds__(256) void split_w_kernel(const float* __restrict__ W) {
    int i = blockIdx.x * 256 + threadIdx.x;
    if (i >= N_TYPES * IN_CH * D_OUT) return;
    int t = i >> 14, rem = i & 16383, k = rem >> 7, o = rem & 127;
    float v = W[i];
    __nv_bfloat16 h = __float2bfloat16(v);
    __nv_bfloat16 l = __float2bfloat16(v - __bfloat162float(h));
    size_t idx = ((size_t)t * D_OUT + o) * IN_CH + k;
    g_wh[idx] = h;
    g_wl[idx] = l;
}

/* ============================================================================
 * K1: HMMA (mma.sync bf16) GEMM: xt[t] = x @ W[t], 3-term split.
 * Epilogue stores fp32 (g_xt) + fp16 message copy (g_xt_h).
 * ==========================================================================*/
#define TSTR 136
#define SM_TILE (128 * TSTR * 2)
#define SMA_H 0
#define SMA_L (SM_TILE)
#define SMB_H (2 * SM_TILE)
#define SMB_L (3 * SM_TILE)
#define SM_GEMM_TOTAL (4 * SM_TILE)

__device__ __forceinline__ void ldm_x4(uint32_t addr, uint32_t* r) {
    asm volatile("ldmatrix.sync.aligned.m8n8.x4.shared.b16 {%0,%1,%2,%3}, [%4];"
                 : "=r"(r[0]), "=r"(r[1]), "=r"(r[2]), "=r"(r[3]) : "r"(addr));
}
__device__ __forceinline__ void mma_bf16(float* c, const uint32_t* a, const uint32_t* b) {
    asm volatile(
        "mma.sync.aligned.m16n8k16.row.col.f32.bf16.bf16.f32 "
        "{%0,%1,%2,%3}, {%4,%5,%6,%7}, {%8,%9}, {%0,%1,%2,%3};"
        : "+f"(c[0]), "+f"(c[1]), "+f"(c[2]), "+f"(c[3])
        : "r"(a[0]), "r"(a[1]), "r"(a[2]), "r"(a[3]), "r"(b[0]), "r"(b[1]));
}

__global__ __launch_bounds__(256) void gemm_mma_kernel(const float* __restrict__ x) {
    extern __shared__ char smem[];
    uint32_t sb = smem_u32(smem);
    const int tid  = threadIdx.x;
    const int wid  = tid >> 5, lane = tid & 31;
    const int n0   = blockIdx.x * 128;
    const int t    = blockIdx.y;
    const int wm   = wid & 3, wn = wid >> 2;
    const int RM   = wm * 32, CN = wn * 64;

    for (int f = tid; f < 4096; f += 256) {
        int row = f >> 5, c4 = f & 31;
        float4 v = make_float4(0.f, 0.f, 0.f, 0.f);
        if (n0 + row < N_NODES)
            v = *(const float4*)(x + (size_t)(n0 + row) * IN_CH + c4 * 4);
        __nv_bfloat16 h[4], l[4];
        float ff[4] = {v.x, v.y, v.z, v.w};
#pragma unroll
        for (int q = 0; q < 4; q++) {
            h[q] = __float2bfloat16(ff[q]);
            l[q] = __float2bfloat16(ff[q] - __bfloat162float(h[q]));
        }
        uint32_t off = (uint32_t)row * (TSTR * 2) + c4 * 8;
        *(uint2*)(smem + SMA_H + off) = *(uint2*)h;
        *(uint2*)(smem + SMA_L + off) = *(uint2*)l;
    }
    for (int f = tid; f < 2048; f += 256) {
        int o = f >> 4, c8 = f & 15;
        uint32_t off = (uint32_t)o * (TSTR * 2) + c8 * 16;
        *(uint4*)(smem + SMB_H + off) =
            *(const uint4*)(g_wh + ((size_t)t * D_OUT + o) * IN_CH + c8 * 8);
        *(uint4*)(smem + SMB_L + off) =
            *(const uint4*)(g_wl + ((size_t)t * D_OUT + o) * IN_CH + c8 * 8);
    }
    __syncthreads();

    int a_row = RM + ((lane >> 3) & 1) * 8 + (lane & 7);
    int a_c8  = (lane >> 4) * 8;
    uint32_t aH = sb + SMA_H + a_row * (TSTR * 2) + a_c8 * 2;
    uint32_t aL = sb + SMA_L + a_row * (TSTR * 2) + a_c8 * 2;
    int b_row = CN + (lane >> 4) * 8 + (lane & 7);
    int b_c8  = ((lane >> 3) & 1) * 8;
    uint32_t bH = sb + SMB_H + b_row * (TSTR * 2) + b_c8 * 2;
    uint32_t bL = sb + SMB_L + b_row * (TSTR * 2) + b_c8 * 2;

    float acc[2][8][4];
#pragma unroll
    for (int mi = 0; mi < 2; mi++)
#pragma unroll
        for (int ni = 0; ni < 8; ni++)
#pragma unroll
            for (int q = 0; q < 4; q++) acc[mi][ni][q] = 0.f;

#pragma unroll
    for (int kk = 0; kk < 8; kk++) {
        uint32_t ah[2][4], al[2][4], bh[8][2], bl[8][2];
#pragma unroll
        for (int mi = 0; mi < 2; mi++) {
            ldm_x4(aH + mi * 16 * (TSTR * 2) + kk * 32, ah[mi]);
            ldm_x4(aL + mi * 16 * (TSTR * 2) + kk * 32, al[mi]);
        }
#pragma unroll
        for (int p = 0; p < 4; p++) {
            uint32_t rh[4], rl[4];
            ldm_x4(bH + p * 16 * (TSTR * 2) + kk * 32, rh);
            ldm_x4(bL + p * 16 * (TSTR * 2) + kk * 32, rl);
            bh[2 * p][0] = rh[0]; bh[2 * p][1] = rh[1];
            bh[2 * p + 1][0] = rh[2]; bh[2 * p + 1][1] = rh[3];
            bl[2 * p][0] = rl[0]; bl[2 * p][1] = rl[1];
            bl[2 * p + 1][0] = rl[2]; bl[2 * p + 1][1] = rl[3];
        }
#pragma unroll
        for (int mi = 0; mi < 2; mi++)
#pragma unroll
            for (int ni = 0; ni < 8; ni++) {
                mma_bf16(acc[mi][ni], ah[mi], bh[ni]);
                mma_bf16(acc[mi][ni], ah[mi], bl[ni]);
                mma_bf16(acc[mi][ni], al[mi], bh[ni]);
            }
    }

    int qrow = lane >> 2, qcol = (lane & 3) * 2;
#pragma unroll
    for (int mi = 0; mi < 2; mi++) {
        int r0 = n0 + RM + mi * 16 + qrow;
        int r1 = r0 + 8;
#pragma unroll
        for (int ni = 0; ni < 8; ni++) {
            int col = CN + ni * 8 + qcol;
            if (r0 < N_NODES) {
                size_t base = ((size_t)t * N_NODES + r0) * D_OUT + col;
                *(float2*)(g_xt + base) = make_float2(acc[mi][ni][0], acc[mi][ni][1]);
                *(__half2*)(g_xt_h + base) =
                    __floats2half2_rn(acc[mi][ni][0], acc[mi][ni][1]);
            }
            if (r1 < N_NODES) {
                size_t base = ((size_t)t * N_NODES + r1) * D_OUT + col;
                *(float2*)(g_xt + base) = make_float2(acc[mi][ni][2], acc[mi][ni][3]);
                *(__half2*)(g_xt_h + base) =
                    __floats2half2_rn(acc[mi][ni][2], acc[mi][ni][3]);
            }
        }
    }
}

/* ============================================================================
 * K2: per-(type,node,head) endpoint scores (row stride 20)
 * ==========================================================================*/
__global__ __launch_bounds__(256) void score_kernel(const float* __restrict__ att) {
    __shared__ float att_s[N_CONF * HEADS * 2 * OUT_CH];
    for (int i = threadIdx.x; i < N_CONF * HEADS * 2 * OUT_CH; i += 256)
        att_s[i] = att[i];
    __syncthreads();

    int id = blockIdx.x * 256 + threadIdx.x;
    if (id >= SEG * HEADS) return;
    int h  = id & 3;
    int nn = id >> 2;

    const float4* v4 = (const float4*)(g_xt + (size_t)nn * D_OUT + h * 32);
    float si[5] = {0, 0, 0, 0, 0}, sj[5] = {0, 0, 0, 0, 0};
#pragma unroll
    for (int q = 0; q < 8; q++) {
        float4 v = v4[q];
#pragma unroll
        for (int k = 0; k < N_CONF; k++) {
            float4 ai = ((const float4*)att_s)[(k * HEADS + h) * 16 + q];
            float4 aj = ((const float4*)att_s)[(k * HEADS + h) * 16 + 8 + q];
            si[k] += v.x * ai.x + v.y * ai.y + v.z * ai.z + v.w * ai.w;
            sj[k] += v.x * aj.x + v.y * aj.y + v.z * aj.z + v.w * aj.w;
        }
    }
    float* so_i = g_si + (size_t)nn * SROW + h * N_CONF;
    float* so_j = g_sj + (size_t)nn * SROW + h * N_CONF;
#pragma unroll
    for (int k = 0; k < N_CONF; k++) { so_i[k] = si[k]; so_j[k] = sj[k]; }
}

/* ============================================================================
 * CSR build
 * ==========================================================================*/
__global__ void hist_kernel(const int* __restrict__ ei, const int* __restrict__ et) {
    int e = blockIdx.x * 256 + threadIdx.x;
    if (e >= N_EDGES) return;
    int d = ei[N_EDGES + e];
    int t = et[e];
    atomicAdd(&g_cnt[d * 4 + t], 1);
}

__device__ __forceinline__ int block_scan_1024(int v, int* smem32, int* tot) {
    int lane = threadIdx.x & 31, w = threadIdx.x >> 5;
    int inc = v;
#pragma unroll
    for (int o = 1; o < 32; o <<= 1) {
        int u = __shfl_up_sync(0xffffffffu, inc, o);
        if (lane >= o) inc += u;
    }
    if (lane == 31) smem32[w] = inc;
    __syncthreads();
    if (w == 0) {
        int ws = smem32[lane];
#pragma unroll
        for (int o = 1; o < 32; o <<= 1) {
            int u = __shfl_up_sync(0xffffffffu, ws, o);
            if (lane >= o) ws += u;
        }
        smem32[lane] = ws;
    }
    __syncthreads();
    int base = (w == 0) ? 0 : smem32[w - 1];
    *tot = smem32[31];
    return inc + base;
}

__global__ __launch_bounds__(1024) void scan_phase1() {
    int idx = blockIdx.x * 1024 + threadIdx.x;
    int v = (idx < SEG) ? g_cnt[idx] : 0;
    __shared__ int smem32[32];
    int tot;
    block_scan_1024(v, smem32, &tot);
    if (threadIdx.x == 0) g_bsum[blockIdx.x] = tot;
}

__global__ __launch_bounds__(256) void scan_phase2() {
    __shared__ int smem32[32];
    int v = (threadIdx.x < SCAN_BLOCKS) ? g_bsum[threadIdx.x] : 0;
    int lane = threadIdx.x & 31, w = threadIdx.x >> 5;
    int inc = v;
#pragma unroll
    for (int o = 1; o < 32; o <<= 1) {
        int u = __shfl_up_sync(0xffffffffu, inc, o);
        if (lane >= o) inc += u;
    }
    if (lane == 31) smem32[w] = inc;
    __syncthreads();
    if (w == 0) {
        int ws = (lane < 8) ? smem32[lane] : 0;
#pragma unroll
        for (int o = 1; o < 8; o <<= 1) {
            int u = __shfl_up_sync(0xffffffffu, ws, o);
            if (lane >= o) ws += u;
        }
        if (lane < 8) smem32[lane] = ws;
    }
    __syncthreads();
    int base = (w == 0) ? 0 : smem32[w - 1];
    int excl = inc + base - v;
    if (threadIdx.x < SCAN_BLOCKS) g_bsum[threadIdx.x] = excl;
}

__global__ __launch_bounds__(1024) void scan_phase3() {
    int idx = blockIdx.x * 1024 + threadIdx.x;
    int v = (idx < SEG) ? g_cnt[idx] : 0;
    __shared__ int smem32[32];
    int tot;
    int inc = block_scan_1024(v, smem32, &tot);
    int excl = inc - v + g_bsum[blockIdx.x];
    if (idx < SEG) {
        g_offs[idx]   = excl;
        g_cursor[idx] = excl;
        if (idx == SEG - 1) g_offs[SEG] = excl + v;
    }
}

__global__ void scatter_kernel(const int* __restrict__ ei, const int* __restrict__ et) {
    int e = blockIdx.x * 256 + threadIdx.x;
    if (e >= N_EDGES) return;
    int src = ei[e];
    int d   = ei[N_EDGES + e];
    int t   = et[e];
    int pos = atomicAdd(&g_cursor[d * 4 + t], 1);
    g_rec[pos] = src | (t << 16);
}

/* ============================================================================
 * K4: one warp per dst node. fp16 message gather; fp32 self/bias.
 * ==========================================================================*/
__global__ __launch_bounds__(256, 4) void node_kernel(const float* __restrict__ conf,
                                                      const float* __restrict__ eimp,
                                                      const float* __restrict__ bias,
                                                      float* __restrict__ out) {
    const unsigned FULL = 0xffffffffu;
    __shared__ float w_s[8][32][4];
    __shared__ int   r_s[8][32];
    __shared__ float md[8][32];
    int gw   = (blockIdx.x * blockDim.x + threadIdx.x) >> 5;
    int wib  = threadIdx.x >> 5;
    int lane = threadIdx.x & 31;
    if (gw >= N_NODES) return;
    const int dst = gw;
    const int hl  = lane >> 3;

    float c0 = conf[0], c1 = conf[1], c2 = conf[2], c3 = conf[3], c4 = conf[4];
    float mx = fmaxf(fmaxf(fmaxf(c0, c1), fmaxf(c2, c3)), c4);
    float e0 = __expf(c0 - mx), e1 = __expf(c1 - mx), e2 = __expf(c2 - mx);
    float e3 = __expf(c3 - mx), e4 = __expf(c4 - mx);
    float inv = 1.f / (e0 + e1 + e2 + e3 + e4);
    float pk[5] = {e0 * inv, e1 * inv, e2 * inv, e3 * inv, e4 * inv};
    float eim[4] = {eimp[0], eimp[1], eimp[2], eimp[3]};

    int s0 = g_offs[dst * 4];
    int s1 = g_offs[dst * 4 + 4];
    int total = s1 - s0;

    float4 acc = make_float4(0.f, 0.f, 0.f, 0.f);

    if (total <= 32) {
        /* ------------------------------ FAST PATH ------------------------ */
        bool act = lane < total;
        int pack = act ? g_rec[s0 + lane] : 0;
        int myt  = pack >> 16;
        int src  = pack & 0xFFFF;

        /* incremental a0 accumulation (low register pressure) */
        float a0[4] = {0.f, 0.f, 0.f, 0.f};
        {
            const float4* sip = (const float4*)(g_si + ((size_t)myt * N_NODES + dst) * SROW);
            const float4* sjp = (const float4*)(g_sj + ((size_t)myt * N_NODES + src) * SROW);
#pragma unroll
            for (int q = 0; q < 5; q++) {
                float4 u = sip[q];
                float4 v = sjp[q];
                float s[4] = {u.x + v.x, u.y + v.y, u.z + v.z, u.w + v.w};
#pragma unroll
                for (int j = 0; j < 4; j++) {
                    const int idx = q * 4 + j;       /* = h*5 + k */
                    const int h = idx / 5, k = idx - h * 5;
                    float val = s[j];
                    val = (val > 0.f) ? val : 0.2f * val;
                    a0[h] += pk[k] * val;
                }
            }
        }

        /* exp (no max shift; scores O(1)); inclusive prefix scan per head */
        float e[4], P[4];
#pragma unroll
        for (int h = 0; h < 4; h++) {
            e[h] = act ? __expf(a0[h]) : 0.f;
            P[h] = e[h];
#pragma unroll
            for (int o = 1; o < 32; o <<= 1) {
                float u = __shfl_up_sync(FULL, P[h], o);
                if (lane >= o) P[h] += u;
            }
        }

        unsigned bb0 = __ballot_sync(FULL, act && (myt & 1));
        unsigned bb1 = __ballot_sync(FULL, act && (myt & 2));
        unsigned amask = (total >= 32) ? 0xffffffffu : ((1u << total) - 1u);
        unsigned bmy = ((myt & 1) ? bb0 : ~bb0) & ((myt & 2) ? bb1 : ~bb1) & amask;
        int hi = (31 - __clz(bmy | 1u)) & 31;
        int lo = __ffs(bmy) - 1;

        float es = sel4(eim, myt);
        float w[4];
#pragma unroll
        for (int h = 0; h < 4; h++) {
            float ph = __shfl_sync(FULL, P[h], hi);
            float pl = __shfl_sync(FULL, P[h], (lo - 1) & 31);
            float dh = ph - (lo > 0 ? pl : 0.f);
            w[h] = act ? e[h] * es / dh : 0.f;
        }

        *(float4*)&w_s[wib][lane][0] = make_float4(w[0], w[1], w[2], w[3]);
        r_s[wib][lane] = myt * N_NODES + src;
        __syncwarp();

        /* 8-deep pipelined fp16 accumulate: uint2/lane = 4 channels */
        int nb = (total + 7) >> 3;
#pragma unroll 1
        for (int b = 0; b < nb; b++) {
            int q0 = b * 8;
            int cnt = total - q0;
            int   rr[8];
            float w8[8];
#pragma unroll
            for (int j = 0; j < 8; j++) {
                int q = q0 + ((j < cnt) ? j : 0);
                rr[j] = r_s[wib][q];
                w8[j] = (j < cnt) ? w_s[wib][q][hl] : 0.f;
            }
            uint2 hv[8];
#pragma unroll
            for (int j = 0; j < 8; j++)
                hv[j] = ((const uint2*)(g_xt_h + ((size_t)rr[j] << 7)))[lane];
#pragma unroll
            for (int j = 0; j < 8; j++) {
                float2 f01 = __half22float2(*(const __half2*)&hv[j].x);
                float2 f23 = __half22float2(*(const __half2*)&hv[j].y);
                acc.x += w8[j] * f01.x;
                acc.y += w8[j] * f01.y;
                acc.z += w8[j] * f23.x;
                acc.w += w8[j] * f23.y;
            }
        }
    } else {
        /* ------------------------------ SLOW PATH ------------------------ */
        bool act = lane < total;
        int pack = act ? g_rec[s0 + lane] : 0;
        int myt  = pack >> 16;
        int src  = pack & 0xFFFF;

        float a0[4];
        {
            const float* sirow = g_si + ((size_t)myt * N_NODES + dst) * SROW;
            const float* sjrow = g_sj + ((size_t)myt * N_NODES + src) * SROW;
#pragma unroll
            for (int h = 0; h < 4; h++) {
                float ah = 0.f;
#pragma unroll
                for (int k = 0; k < N_CONF; k++) {
                    float v = sirow[h * 5 + k] + sjrow[h * 5 + k];
                    v = (v > 0.f) ? v : 0.2f * v;
                    ah += pk[k] * v;
                }
                a0[h] = ah;
            }
        }
#pragma unroll
        for (int tt = 0; tt < 4; tt++)
#pragma unroll
            for (int hh = 0; hh < 4; hh++) {
                float v = (act && myt == tt) ? a0[hh] : -1e30f;
#pragma unroll
                for (int o = 16; o; o >>= 1) v = fmaxf(v, __shfl_xor_sync(FULL, v, o));
                md[wib][tt * 4 + hh] = v;
            }
        __syncwarp();
#pragma unroll 1
        for (int eb = 32; eb < total; eb += 32) {
            bool a2 = eb + lane < total;
            int pk2 = a2 ? g_rec[s0 + eb + lane] : 0;
            int t2 = pk2 >> 16, s2 = pk2 & 0xFFFF;
            const float* sirow = g_si + ((size_t)t2 * N_NODES + dst) * SROW;
            const float* sjrow = g_sj + ((size_t)t2 * N_NODES + s2) * SROW;
            float aa[4];
#pragma unroll
            for (int h = 0; h < 4; h++) {
                float ah = 0.f;
#pragma unroll
                for (int k = 0; k < N_CONF; k++) {
                    float v = sirow[h * 5 + k] + sjrow[h * 5 + k];
                    v = (v > 0.f) ? v : 0.2f * v;
                    ah += pk[k] * v;
                }
                aa[h] = ah;
            }
#pragma unroll
            for (int tt = 0; tt < 4; tt++)
#pragma unroll
                for (int hh = 0; hh < 4; hh++) {
                    float v = (a2 && t2 == tt) ? aa[hh] : -1e30f;
#pragma unroll
                    for (int o = 16; o; o >>= 1) v = fmaxf(v, __shfl_xor_sync(FULL, v, o));
                    if (v > md[wib][tt * 4 + hh]) md[wib][tt * 4 + hh] = v;
                }
            __syncwarp();
        }
#pragma unroll
        for (int tt = 0; tt < 4; tt++)
#pragma unroll
            for (int hh = 0; hh < 4; hh++) {
                float v = (act && myt == tt) ? __expf(a0[hh] - md[wib][tt * 4 + hh]) : 0.f;
#pragma unroll
                for (int o = 16; o; o >>= 1) v += __shfl_xor_sync(FULL, v, o);
                md[wib][16 + tt * 4 + hh] = v;
            }
        __syncwarp();
#pragma unroll 1
        for (int eb = 32; eb < total; eb += 32) {
            bool a2 = eb + lane < total;
            int pk2 = a2 ? g_rec[s0 + eb + lane] : 0;
            int t2 = pk2 >> 16, s2 = pk2 & 0xFFFF;
            const float* sirow = g_si + ((size_t)t2 * N_NODES + dst) * SROW;
            const float* sjrow = g_sj + ((size_t)t2 * N_NODES + s2) * SROW;
            float aa[4];
#pragma unroll
            for (int h = 0; h < 4; h++) {
                float ah = 0.f;
#pragma unroll
                for (int k = 0; k < N_CONF; k++) {
                    float v = sirow[h * 5 + k] + sjrow[h * 5 + k];
                    v = (v > 0.f) ? v : 0.2f * v;
                    ah += pk[k] * v;
                }
                aa[h] = ah;
            }
#pragma unroll
            for (int tt = 0; tt < 4; tt++)
#pragma unroll
                for (int hh = 0; hh < 4; hh++) {
                    float v = (a2 && t2 == tt) ? __expf(aa[hh] - md[wib][tt * 4 + hh]) : 0.f;
#pragma unroll
                    for (int o = 16; o; o >>= 1) v += __shfl_xor_sync(FULL, v, o);
                    md[wib][16 + tt * 4 + hh] += v;
                }
            __syncwarp();
        }
#pragma unroll 1
        for (int q = 0; q < total; q++) {
            int pk2 = g_rec[s0 + q];
            int t = pk2 >> 16, s = pk2 & 0xFFFF;
            const float* sirow = g_si + ((size_t)t * N_NODES + dst) * SROW + hl * 5;
            const float* sjrow = g_sj + ((size_t)t * N_NODES + s) * SROW + hl * 5;
            float aa = 0.f;
#pragma unroll
            for (int k = 0; k < N_CONF; k++) {
                float v = sirow[k] + sjrow[k];
                v = (v > 0.f) ? v : 0.2f * v;
                aa += pk[k] * v;
            }
            float ww = __expf(aa - md[wib][t * 4 + hl]) * sel4(eim, t)
                       / md[wib][16 + t * 4 + hl];
            uint2 hv = ((const uint2*)(g_xt_h + (((size_t)t * N_NODES + s) << 7)))[lane];
            float2 f01 = __half22float2(*(const __half2*)&hv.x);
            float2 f23 = __half22float2(*(const __half2*)&hv.y);
            acc.x += ww * f01.x;
            acc.y += ww * f01.y;
            acc.z += ww * f23.x;
            acc.w += ww * f23.y;
        }
    }

    float4 self = ((const float4*)(g_xt + ((size_t)dst << 7)))[lane];
    float4 bb   = ((const float4*)bias)[lane];
    float4 o;
    o.x = acc.x + self.x + bb.x;
    o.y = acc.y + self.y + bb.y;
    o.z = acc.z + self.z + bb.z;
    o.w = acc.w + self.w + bb.w;
    ((float4*)(out + (size_t)dst * D_OUT))[lane] = o;
}

/* ============================================================================ */
extern "C" void kernel_launch(void* const* d_in, const int* in_sizes, int n_in,
                              void* d_out, int out_size) {
    const float* x    = (const float*)d_in[0];
    const int*   ei   = (const int*)d_in[1];
    const int*   et   = (const int*)d_in[2];
    const float* W    = (const float*)d_in[3];
    const float* att  = (const float*)d_in[4];
    const float* conf = (const float*)d_in[5];
    const float* eimp = (const float*)d_in[6];
    const float* bias = (const float*)d_in[7];
    float*       out  = (float*)d_out;

    void* cntp = nullptr;
    cudaGetSymbolAddress(&cntp, g_cnt);
    cudaMemsetAsync(cntp, 0, SEG * sizeof(int));

    hist_kernel<<<(N_EDGES + 255) / 256, 256>>>(ei, et);
    scan_phase1<<<SCAN_BLOCKS, 1024>>>();
    scan_phase2<<<1, 256>>>();
    scan_phase3<<<SCAN_BLOCKS, 1024>>>();
    scatter_kernel<<<(N_EDGES + 255) / 256, 256>>>(ei, et);

    split_w_kernel<<<(N_TYPES * IN_CH * D_OUT + 255) / 256, 256>>>(W);

    cudaFuncSetAttribute(gemm_mma_kernel,
                         cudaFuncAttributeMaxDynamicSharedMemorySize, SM_GEMM_TOTAL);
    dim3 gg((N_NODES + 127) / 128, N_TYPES);
    gemm_mma_kernel<<<gg, 256, SM_GEMM_TOTAL>>>(x);

    score_kernel<<<(SEG * HEADS + 255) / 256, 256>>>(att);
    node_kernel<<<(N_NODES * 32 + 255) / 256, 256>>>(conf, eimp, bias, out);
}

// round 10
// speedup vs baseline: 1.1143x; 1.1143x over previous
#include <cuda_runtime.h>
#include <cuda_bf16.h>
#include <cuda_fp16.h>
#include <cstdint>
#include <math.h>

#define N_NODES 50000
#define N_EDGES 800000
#define IN_CH 128
#define OUT_CH 32
#define HEADS 4
#define N_TYPES 4
#define N_CONF 5
#define D_OUT 128                 /* HEADS*OUT_CH */
#define SEG (N_TYPES * N_NODES)   /* 200000 (dst,type) segments */
#define SCAN_BLOCKS ((SEG + 1023) / 1024)   /* 196 */
#define SROW 20                   /* floats per (t,n) score row */

/* ------------------------- device scratch (static, no allocation) ---------- */
__device__ __half g_xt_h[(size_t)N_TYPES * N_NODES * D_OUT];       /* 51.2 MB ONLY copy */
__device__ float g_si[(size_t)N_TYPES * N_NODES * SROW];           /* 16 MB */
__device__ float g_sj[(size_t)N_TYPES * N_NODES * SROW];           /* 16 MB */
__device__ int   g_cnt[SEG];
__device__ int   g_offs[SEG + 1];
__device__ int   g_cursor[SEG];
__device__ int   g_rec[N_EDGES];                                   /* 3.2 MB, src|t<<16 */
__device__ int   g_bsum[SCAN_BLOCKS];
__device__ __nv_bfloat16 g_wh[(size_t)N_TYPES * D_OUT * IN_CH];    /* [t][o][k] */
__device__ __nv_bfloat16 g_wl[(size_t)N_TYPES * D_OUT * IN_CH];

__device__ __forceinline__ uint32_t smem_u32(const void* p) {
    uint32_t a;
    asm("{ .reg .u64 t; cvta.to.shared.u64 t, %1; cvt.u32.u64 %0, t; }"
        : "=r"(a) : "l"(p));
    return a;
}
__device__ __forceinline__ float sel4(const float* a, int t) {
    return t == 0 ? a[0] : t == 1 ? a[1] : t == 2 ? a[2] : a[3];
}

/* ============================================================================
 * K0: split + transpose W: [t][k][o] fp32 -> [t][o][k] bf16 hi/lo
 * ==========================================================================*/
__global__ __launch_bounds__(256) void split_w_kernel(const float* __restrict__ W) {
    int i = blockIdx.x * 256 + threadIdx.x;
    if (i >= N_TYPES * IN_CH * D_OUT) return;
    int t = i >> 14, rem = i & 16383, k = rem >> 7, o = rem & 127;
    float v = W[i];
    __nv_bfloat16 h = __float2bfloat16(v);
    __nv_bfloat16 l = __float2bfloat16(v - __bfloat162float(h));
    size_t idx = ((size_t)t * D_OUT + o) * IN_CH + k;
    g_wh[idx] = h;
    g_wl[idx] = l;
}

/* ============================================================================
 * K1: HMMA (mma.sync bf16) GEMM: xt[t] = x @ W[t], 3-term split.
 * Epilogue stores fp16 ONLY (halved writes, L2-resident xt).
 * ==========================================================================*/
#define TSTR 136
#define SM_TILE (128 * TSTR * 2)
#define SMA_H 0
#define SMA_L (SM_TILE)
#define SMB_H (2 * SM_TILE)
#define SMB_L (3 * SM_TILE)
#define SM_GEMM_TOTAL (4 * SM_TILE)

__device__ __forceinline__ void ldm_x4(uint32_t addr, uint32_t* r) {
    asm volatile("ldmatrix.sync.aligned.m8n8.x4.shared.b16 {%0,%1,%2,%3}, [%4];"
                 : "=r"(r[0]), "=r"(r[1]), "=r"(r[2]), "=r"(r[3]) : "r"(addr));
}
__device__ __forceinline__ void mma_bf16(float* c, const uint32_t* a, const uint32_t* b) {
    asm volatile(
        "mma.sync.aligned.m16n8k16.row.col.f32.bf16.bf16.f32 "
        "{%0,%1,%2,%3}, {%4,%5,%6,%7}, {%8,%9}, {%0,%1,%2,%3};"
        : "+f"(c[0]), "+f"(c[1]), "+f"(c[2]), "+f"(c[3])
        : "r"(a[0]), "r"(a[1]), "r"(a[2]), "r"(a[3]), "r"(b[0]), "r"(b[1]));
}

__global__ __launch_bounds__(256) void gemm_mma_kernel(const float* __restrict__ x) {
    extern __shared__ char smem[];
    uint32_t sb = smem_u32(smem);
    const int tid  = threadIdx.x;
    const int wid  = tid >> 5, lane = tid & 31;
    const int n0   = blockIdx.x * 128;
    const int t    = blockIdx.y;
    const int wm   = wid & 3, wn = wid >> 2;
    const int RM   = wm * 32, CN = wn * 64;

    for (int f = tid; f < 4096; f += 256) {
        int row = f >> 5, c4 = f & 31;
        float4 v = make_float4(0.f, 0.f, 0.f, 0.f);
        if (n0 + row < N_NODES)
            v = *(const float4*)(x + (size_t)(n0 + row) * IN_CH + c4 * 4);
        __nv_bfloat16 h[4], l[4];
        float ff[4] = {v.x, v.y, v.z, v.w};
#pragma unroll
        for (int q = 0; q < 4; q++) {
            h[q] = __float2bfloat16(ff[q]);
            l[q] = __float2bfloat16(ff[q] - __bfloat162float(h[q]));
        }
        uint32_t off = (uint32_t)row * (TSTR * 2) + c4 * 8;
        *(uint2*)(smem + SMA_H + off) = *(uint2*)h;
        *(uint2*)(smem + SMA_L + off) = *(uint2*)l;
    }
    for (int f = tid; f < 2048; f += 256) {
        int o = f >> 4, c8 = f & 15;
        uint32_t off = (uint32_t)o * (TSTR * 2) + c8 * 16;
        *(uint4*)(smem + SMB_H + off) =
            *(const uint4*)(g_wh + ((size_t)t * D_OUT + o) * IN_CH + c8 * 8);
        *(uint4*)(smem + SMB_L + off) =
            *(const uint4*)(g_wl + ((size_t)t * D_OUT + o) * IN_CH + c8 * 8);
    }
    __syncthreads();

    int a_row = RM + ((lane >> 3) & 1) * 8 + (lane & 7);
    int a_c8  = (lane >> 4) * 8;
    uint32_t aH = sb + SMA_H + a_row * (TSTR * 2) + a_c8 * 2;
    uint32_t aL = sb + SMA_L + a_row * (TSTR * 2) + a_c8 * 2;
    int b_row = CN + (lane >> 4) * 8 + (lane & 7);
    int b_c8  = ((lane >> 3) & 1) * 8;
    uint32_t bH = sb + SMB_H + b_row * (TSTR * 2) + b_c8 * 2;
    uint32_t bL = sb + SMB_L + b_row * (TSTR * 2) + b_c8 * 2;

    float acc[2][8][4];
#pragma unroll
    for (int mi = 0; mi < 2; mi++)
#pragma unroll
        for (int ni = 0; ni < 8; ni++)
#pragma unroll
            for (int q = 0; q < 4; q++) acc[mi][ni][q] = 0.f;

#pragma unroll
    for (int kk = 0; kk < 8; kk++) {
        uint32_t ah[2][4], al[2][4], bh[8][2], bl[8][2];
#pragma unroll
        for (int mi = 0; mi < 2; mi++) {
            ldm_x4(aH + mi * 16 * (TSTR * 2) + kk * 32, ah[mi]);
            ldm_x4(aL + mi * 16 * (TSTR * 2) + kk * 32, al[mi]);
        }
#pragma unroll
        for (int p = 0; p < 4; p++) {
            uint32_t rh[4], rl[4];
            ldm_x4(bH + p * 16 * (TSTR * 2) + kk * 32, rh);
            ldm_x4(bL + p * 16 * (TSTR * 2) + kk * 32, rl);
            bh[2 * p][0] = rh[0]; bh[2 * p][1] = rh[1];
            bh[2 * p + 1][0] = rh[2]; bh[2 * p + 1][1] = rh[3];
            bl[2 * p][0] = rl[0]; bl[2 * p][1] = rl[1];
            bl[2 * p + 1][0] = rl[2]; bl[2 * p + 1][1] = rl[3];
        }
#pragma unroll
        for (int mi = 0; mi < 2; mi++)
#pragma unroll
            for (int ni = 0; ni < 8; ni++) {
                mma_bf16(acc[mi][ni], ah[mi], bh[ni]);
                mma_bf16(acc[mi][ni], ah[mi], bl[ni]);
                mma_bf16(acc[mi][ni], al[mi], bh[ni]);
            }
    }

    int qrow = lane >> 2, qcol = (lane & 3) * 2;
#pragma unroll
    for (int mi = 0; mi < 2; mi++) {
        int r0 = n0 + RM + mi * 16 + qrow;
        int r1 = r0 + 8;
#pragma unroll
        for (int ni = 0; ni < 8; ni++) {
            int col = CN + ni * 8 + qcol;
            if (r0 < N_NODES)
                *(__half2*)(g_xt_h + ((size_t)t * N_NODES + r0) * D_OUT + col) =
                    __floats2half2_rn(acc[mi][ni][0], acc[mi][ni][1]);
            if (r1 < N_NODES)
                *(__half2*)(g_xt_h + ((size_t)t * N_NODES + r1) * D_OUT + col) =
                    __floats2half2_rn(acc[mi][ni][2], acc[mi][ni][3]);
        }
    }
}

/* ============================================================================
 * K2: per-(type,node,head) endpoint scores from fp16 xt (row stride 20 out)
 * ==========================================================================*/
__global__ __launch_bounds__(256) void score_kernel(const float* __restrict__ att) {
    __shared__ float att_s[N_CONF * HEADS * 2 * OUT_CH];
    for (int i = threadIdx.x; i < N_CONF * HEADS * 2 * OUT_CH; i += 256)
        att_s[i] = att[i];
    __syncthreads();

    int id = blockIdx.x * 256 + threadIdx.x;
    if (id >= SEG * HEADS) return;
    int h  = id & 3;
    int nn = id >> 2;

    const uint2* v2 = (const uint2*)(g_xt_h + (size_t)nn * D_OUT + h * 32);
    float si[5] = {0, 0, 0, 0, 0}, sj[5] = {0, 0, 0, 0, 0};
#pragma unroll
    for (int q = 0; q < 8; q++) {
        uint2 hv = v2[q];
        float2 f01 = __half22float2(*(const __half2*)&hv.x);
        float2 f23 = __half22float2(*(const __half2*)&hv.y);
        float4 v = make_float4(f01.x, f01.y, f23.x, f23.y);
#pragma unroll
        for (int k = 0; k < N_CONF; k++) {
            float4 ai = ((const float4*)att_s)[(k * HEADS + h) * 16 + q];
            float4 aj = ((const float4*)att_s)[(k * HEADS + h) * 16 + 8 + q];
            si[k] += v.x * ai.x + v.y * ai.y + v.z * ai.z + v.w * ai.w;
            sj[k] += v.x * aj.x + v.y * aj.y + v.z * aj.z + v.w * aj.w;
        }
    }
    float* so_i = g_si + (size_t)nn * SROW + h * N_CONF;
    float* so_j = g_sj + (size_t)nn * SROW + h * N_CONF;
#pragma unroll
    for (int k = 0; k < N_CONF; k++) { so_i[k] = si[k]; so_j[k] = sj[k]; }
}

/* ============================================================================
 * CSR build
 * ==========================================================================*/
__global__ void hist_kernel(const int* __restrict__ ei, const int* __restrict__ et) {
    int e = blockIdx.x * 256 + threadIdx.x;
    if (e >= N_EDGES) return;
    int d = ei[N_EDGES + e];
    int t = et[e];
    atomicAdd(&g_cnt[d * 4 + t], 1);
}

__device__ __forceinline__ int block_scan_1024(int v, int* smem32, int* tot) {
    int lane = threadIdx.x & 31, w = threadIdx.x >> 5;
    int inc = v;
#pragma unroll
    for (int o = 1; o < 32; o <<= 1) {
        int u = __shfl_up_sync(0xffffffffu, inc, o);
        if (lane >= o) inc += u;
    }
    if (lane == 31) smem32[w] = inc;
    __syncthreads();
    if (w == 0) {
        int ws = smem32[lane];
#pragma unroll
        for (int o = 1; o < 32; o <<= 1) {
            int u = __shfl_up_sync(0xffffffffu, ws, o);
            if (lane >= o) ws += u;
        }
        smem32[lane] = ws;
    }
    __syncthreads();
    int base = (w == 0) ? 0 : smem32[w - 1];
    *tot = smem32[31];
    return inc + base;
}

__global__ __launch_bounds__(1024) void scan_phase1() {
    int idx = blockIdx.x * 1024 + threadIdx.x;
    int v = (idx < SEG) ? g_cnt[idx] : 0;
    __shared__ int smem32[32];
    int tot;
    block_scan_1024(v, smem32, &tot);
    if (threadIdx.x == 0) g_bsum[blockIdx.x] = tot;
}

__global__ __launch_bounds__(256) void scan_phase2() {
    __shared__ int smem32[32];
    int v = (threadIdx.x < SCAN_BLOCKS) ? g_bsum[threadIdx.x] : 0;
    int lane = threadIdx.x & 31, w = threadIdx.x >> 5;
    int inc = v;
#pragma unroll
    for (int o = 1; o < 32; o <<= 1) {
        int u = __shfl_up_sync(0xffffffffu, inc, o);
        if (lane >= o) inc += u;
    }
    if (lane == 31) smem32[w] = inc;
    __syncthreads();
    if (w == 0) {
        int ws = (lane < 8) ? smem32[lane] : 0;
#pragma unroll
        for (int o = 1; o < 8; o <<= 1) {
            int u = __shfl_up_sync(0xffffffffu, ws, o);
            if (lane >= o) ws += u;
        }
        if (lane < 8) smem32[lane] = ws;
    }
    __syncthreads();
    int base = (w == 0) ? 0 : smem32[w - 1];
    int excl = inc + base - v;
    if (threadIdx.x < SCAN_BLOCKS) g_bsum[threadIdx.x] = excl;
}

__global__ __launch_bounds__(1024) void scan_phase3() {
    int idx = blockIdx.x * 1024 + threadIdx.x;
    int v = (idx < SEG) ? g_cnt[idx] : 0;
    __shared__ int smem32[32];
    int tot;
    int inc = block_scan_1024(v, smem32, &tot);
    int excl = inc - v + g_bsum[blockIdx.x];
    if (idx < SEG) {
        g_offs[idx]   = excl;
        g_cursor[idx] = excl;
        if (idx == SEG - 1) g_offs[SEG] = excl + v;
    }
}

__global__ void scatter_kernel(const int* __restrict__ ei, const int* __restrict__ et) {
    int e = blockIdx.x * 256 + threadIdx.x;
    if (e >= N_EDGES) return;
    int src = ei[e];
    int d   = ei[N_EDGES + e];
    int t   = et[e];
    int pos = atomicAdd(&g_cursor[d * 4 + t], 1);
    g_rec[pos] = src | (t << 16);
}

/* ============================================================================
 * K4: one warp per dst node. fp16 xt gather (L2-resident).
 * ==========================================================================*/
__global__ __launch_bounds__(256, 4) void node_kernel(const float* __restrict__ conf,
                                                      const float* __restrict__ eimp,
                                                      const float* __restrict__ bias,
                                                      float* __restrict__ out) {
    const unsigned FULL = 0xffffffffu;
    __shared__ float w_s[8][32][4];
    __shared__ int   r_s[8][32];
    __shared__ float md[8][32];
    int gw   = (blockIdx.x * blockDim.x + threadIdx.x) >> 5;
    int wib  = threadIdx.x >> 5;
    int lane = threadIdx.x & 31;
    if (gw >= N_NODES) return;
    const int dst = gw;
    const int hl  = lane >> 3;

    float c0 = conf[0], c1 = conf[1], c2 = conf[2], c3 = conf[3], c4 = conf[4];
    float mx = fmaxf(fmaxf(fmaxf(c0, c1), fmaxf(c2, c3)), c4);
    float e0 = __expf(c0 - mx), e1 = __expf(c1 - mx), e2 = __expf(c2 - mx);
    float e3 = __expf(c3 - mx), e4 = __expf(c4 - mx);
    float inv = 1.f / (e0 + e1 + e2 + e3 + e4);
    float pk[5] = {e0 * inv, e1 * inv, e2 * inv, e3 * inv, e4 * inv};
    float eim[4] = {eimp[0], eimp[1], eimp[2], eimp[3]};

    int s0 = g_offs[dst * 4];
    int s1 = g_offs[dst * 4 + 4];
    int total = s1 - s0;

    float4 acc = make_float4(0.f, 0.f, 0.f, 0.f);

    if (total <= 32) {
        /* ------------------------------ FAST PATH ------------------------ */
        bool act = lane < total;
        int pack = act ? g_rec[s0 + lane] : 0;
        int myt  = pack >> 16;
        int src  = pack & 0xFFFF;

        float a0[4] = {0.f, 0.f, 0.f, 0.f};
        {
            const float4* sip = (const float4*)(g_si + ((size_t)myt * N_NODES + dst) * SROW);
            const float4* sjp = (const float4*)(g_sj + ((size_t)myt * N_NODES + src) * SROW);
#pragma unroll
            for (int q = 0; q < 5; q++) {
                float4 u = sip[q];
                float4 v = sjp[q];
                float s[4] = {u.x + v.x, u.y + v.y, u.z + v.z, u.w + v.w};
#pragma unroll
                for (int j = 0; j < 4; j++) {
                    const int idx = q * 4 + j;       /* = h*5 + k */
                    const int h = idx / 5, k = idx - h * 5;
                    float val = s[j];
                    val = (val > 0.f) ? val : 0.2f * val;
                    a0[h] += pk[k] * val;
                }
            }
        }

        float e[4], P[4];
#pragma unroll
        for (int h = 0; h < 4; h++) {
            e[h] = act ? __expf(a0[h]) : 0.f;
            P[h] = e[h];
#pragma unroll
            for (int o = 1; o < 32; o <<= 1) {
                float u = __shfl_up_sync(FULL, P[h], o);
                if (lane >= o) P[h] += u;
            }
        }

        unsigned bb0 = __ballot_sync(FULL, act && (myt & 1));
        unsigned bb1 = __ballot_sync(FULL, act && (myt & 2));
        unsigned amask = (total >= 32) ? 0xffffffffu : ((1u << total) - 1u);
        unsigned bmy = ((myt & 1) ? bb0 : ~bb0) & ((myt & 2) ? bb1 : ~bb1) & amask;
        int hi = (31 - __clz(bmy | 1u)) & 31;
        int lo = __ffs(bmy) - 1;

        float es = sel4(eim, myt);
        float w[4];
#pragma unroll
        for (int h = 0; h < 4; h++) {
            float ph = __shfl_sync(FULL, P[h], hi);
            float pl = __shfl_sync(FULL, P[h], (lo - 1) & 31);
            float dh = ph - (lo > 0 ? pl : 0.f);
            w[h] = act ? e[h] * es / dh : 0.f;
        }

        *(float4*)&w_s[wib][lane][0] = make_float4(w[0], w[1], w[2], w[3]);
        r_s[wib][lane] = myt * N_NODES + src;
        __syncwarp();

        int nb = (total + 7) >> 3;
#pragma unroll 1
        for (int b = 0; b < nb; b++) {
            int q0 = b * 8;
            int cnt = total - q0;
            int   rr[8];
            float w8[8];
#pragma unroll
            for (int j = 0; j < 8; j++) {
                int q = q0 + ((j < cnt) ? j : 0);
                rr[j] = r_s[wib][q];
                w8[j] = (j < cnt) ? w_s[wib][q][hl] : 0.f;
            }
            uint2 hv[8];
#pragma unroll
            for (int j = 0; j < 8; j++)
                hv[j] = ((const uint2*)(g_xt_h + ((size_t)rr[j] << 7)))[lane];
#pragma unroll
            for (int j = 0; j < 8; j++) {
                float2 f01 = __half22float2(*(const __half2*)&hv[j].x);
                float2 f23 = __half22float2(*(const __half2*)&hv[j].y);
                acc.x += w8[j] * f01.x;
                acc.y += w8[j] * f01.y;
                acc.z += w8[j] * f23.x;
                acc.w += w8[j] * f23.y;
            }
        }
    } else {
        /* ------------------------------ SLOW PATH ------------------------ */
        bool act = lane < total;
        int pack = act ? g_rec[s0 + lane] : 0;
        int myt  = pack >> 16;
        int src  = pack & 0xFFFF;

        float a0[4];
        {
            const float* sirow = g_si + ((size_t)myt * N_NODES + dst) * SROW;
            const float* sjrow = g_sj + ((size_t)myt * N_NODES + src) * SROW;
#pragma unroll
            for (int h = 0; h < 4; h++) {
                float ah = 0.f;
#pragma unroll
                for (int k = 0; k < N_CONF; k++) {
                    float v = sirow[h * 5 + k] + sjrow[h * 5 + k];
                    v = (v > 0.f) ? v : 0.2f * v;
                    ah += pk[k] * v;
                }
                a0[h] = ah;
            }
        }
#pragma unroll
        for (int tt = 0; tt < 4; tt++)
#pragma unroll
            for (int hh = 0; hh < 4; hh++) {
                float v = (act && myt == tt) ? a0[hh] : -1e30f;
#pragma unroll
                for (int o = 16; o; o >>= 1) v = fmaxf(v, __shfl_xor_sync(FULL, v, o));
                md[wib][tt * 4 + hh] = v;
            }
        __syncwarp();
#pragma unroll 1
        for (int eb = 32; eb < total; eb += 32) {
            bool a2 = eb + lane < total;
            int pk2 = a2 ? g_rec[s0 + eb + lane] : 0;
            int t2 = pk2 >> 16, s2 = pk2 & 0xFFFF;
            const float* sirow = g_si + ((size_t)t2 * N_NODES + dst) * SROW;
            const float* sjrow = g_sj + ((size_t)t2 * N_NODES + s2) * SROW;
            float aa[4];
#pragma unroll
            for (int h = 0; h < 4; h++) {
                float ah = 0.f;
#pragma unroll
                for (int k = 0; k < N_CONF; k++) {
                    float v = sirow[h * 5 + k] + sjrow[h * 5 + k];
                    v = (v > 0.f) ? v : 0.2f * v;
                    ah += pk[k] * v;
                }
                aa[h] = ah;
            }
#pragma unroll
            for (int tt = 0; tt < 4; tt++)
#pragma unroll
                for (int hh = 0; hh < 4; hh++) {
                    float v = (a2 && t2 == tt) ? aa[hh] : -1e30f;
#pragma unroll
                    for (int o = 16; o; o >>= 1) v = fmaxf(v, __shfl_xor_sync(FULL, v, o));
                    if (v > md[wib][tt * 4 + hh]) md[wib][tt * 4 + hh] = v;
                }
            __syncwarp();
        }
#pragma unroll
        for (int tt = 0; tt < 4; tt++)
#pragma unroll
            for (int hh = 0; hh < 4; hh++) {
                float v = (act && myt == tt) ? __expf(a0[hh] - md[wib][tt * 4 + hh]) : 0.f;
#pragma unroll
                for (int o = 16; o; o >>= 1) v += __shfl_xor_sync(FULL, v, o);
                md[wib][16 + tt * 4 + hh] = v;
            }
        __syncwarp();
#pragma unroll 1
        for (int eb = 32; eb < total; eb += 32) {
            bool a2 = eb + lane < total;
            int pk2 = a2 ? g_rec[s0 + eb + lane] : 0;
            int t2 = pk2 >> 16, s2 = pk2 & 0xFFFF;
            const float* sirow = g_si + ((size_t)t2 * N_NODES + dst) * SROW;
            const float* sjrow = g_sj + ((size_t)t2 * N_NODES + s2) * SROW;
            float aa[4];
#pragma unroll
            for (int h = 0; h < 4; h++) {
                float ah = 0.f;
#pragma unroll
                for (int k = 0; k < N_CONF; k++) {
                    float v = sirow[h * 5 + k] + sjrow[h * 5 + k];
                    v = (v > 0.f) ? v : 0.2f * v;
                    ah += pk[k] * v;
                }
                aa[h] = ah;
            }
#pragma unroll
            for (int tt = 0; tt < 4; tt++)
#pragma unroll
                for (int hh = 0; hh < 4; hh++) {
                    float v = (a2 && t2 == tt) ? __expf(aa[hh] - md[wib][tt * 4 + hh]) : 0.f;
#pragma unroll
                    for (int o = 16; o; o >>= 1) v += __shfl_xor_sync(FULL, v, o);
                    md[wib][16 + tt * 4 + hh] += v;
                }
            __syncwarp();
        }
#pragma unroll 1
        for (int q = 0; q < total; q++) {
            int pk2 = g_rec[s0 + q];
            int t = pk2 >> 16, s = pk2 & 0xFFFF;
            const float* sirow = g_si + ((size_t)t * N_NODES + dst) * SROW + hl * 5;
            const float* sjrow = g_sj + ((size_t)t * N_NODES + s) * SROW + hl * 5;
            float aa = 0.f;
#pragma unroll
            for (int k = 0; k < N_CONF; k++) {
                float v = sirow[k] + sjrow[k];
                v = (v > 0.f) ? v : 0.2f * v;
                aa += pk[k] * v;
            }
            float ww = __expf(aa - md[wib][t * 4 + hl]) * sel4(eim, t)
                       / md[wib][16 + t * 4 + hl];
            uint2 hv = ((const uint2*)(g_xt_h + (((size_t)t * N_NODES + s) << 7)))[lane];
            float2 f01 = __half22float2(*(const __half2*)&hv.x);
            float2 f23 = __half22float2(*(const __half2*)&hv.y);
            acc.x += ww * f01.x;
            acc.y += ww * f01.y;
            acc.z += ww * f23.x;
            acc.w += ww * f23.y;
        }
    }

    /* epilogue: self-loop (fp16 xt row of type 0) + bias */
    uint2 sh = ((const uint2*)(g_xt_h + ((size_t)dst << 7)))[lane];
    float2 s01 = __half22float2(*(const __half2*)&sh.x);
    float2 s23 = __half22float2(*(const __half2*)&sh.y);
    float4 bb  = ((const float4*)bias)[lane];
    float4 o;
    o.x = acc.x + s01.x + bb.x;
    o.y = acc.y + s01.y + bb.y;
    o.z = acc.z + s23.x + bb.z;
    o.w = acc.w + s23.y + bb.w;
    ((float4*)(out + (size_t)dst * D_OUT))[lane] = o;
}

/* ============================================================================ */
extern "C" void kernel_launch(void* const* d_in, const int* in_sizes, int n_in,
                              void* d_out, int out_size) {
    const float* x    = (const float*)d_in[0];
    const int*   ei   = (const int*)d_in[1];
    const int*   et   = (const int*)d_in[2];
    const float* W    = (const float*)d_in[3];
    const float* att  = (const float*)d_in[4];
    const float* conf = (const float*)d_in[5];
    const float* eimp = (const float*)d_in[6];
    const float* bias = (const float*)d_in[7];
    float*       out  = (float*)d_out;

    void* cntp = nullptr;
    cudaGetSymbolAddress(&cntp, g_cnt);
    cudaMemsetAsync(cntp, 0, SEG * sizeof(int));

    hist_kernel<<<(N_EDGES + 255) / 256, 256>>>(ei, et);
    scan_phase1<<<SCAN_BLOCKS, 1024>>>();
    scan_phase2<<<1, 256>>>();
    scan_phase3<<<SCAN_BLOCKS, 1024>>>();
    scatter_kernel<<<(N_EDGES + 255) / 256, 256>>>(ei, et);

    split_w_kernel<<<(N_TYPES * IN_CH * D_OUT + 255) / 256, 256>>>(W);

    cudaFuncSetAttribute(gemm_mma_kernel,
                         cudaFuncAttributeMaxDynamicSharedMemorySize, SM_GEMM_TOTAL);
    dim3 gg((N_NODES + 127) / 128, N_TYPES);
    gemm_mma_kernel<<<gg, 256, SM_GEMM_TOTAL>>>(x);

    score_kernel<<<(SEG * HEADS + 255) / 256, 256>>>(att);
    node_kernel<<<(N_NODES * 32 + 255) / 256, 256>>>(conf, eimp, bias, out);
}